// round 12
// baseline (speedup 1.0000x reference)
#include <cuda_runtime.h>
#include <cuda_fp16.h>
#include <math.h>

#define NMAX   50000
#define E_MAX  1600000
#define F_IN   128
#define F_HID  128
#define F_OUT  40
#define EF     16
#define EH     32
#define SCAN_B 256

// ---------------- scratch (static device globals; no allocs allowed) --------
__device__ int      g_is64;
__device__ unsigned g_pack[E_MAX];       // (row:16 | col:16), clamped
__device__ float    g_ew  [E_MAX];
__device__ float    g_deg [NMAX];
__device__ float    g_dinv[NMAX];
__device__ int      g_cnt [NMAX];
__device__ int      g_rowptr[NMAX + 1];
__device__ int      g_cursor[NMAX];
__device__ int      g_bsum[((NMAX + SCAN_B - 1) / SCAN_B) + 1];
__device__ unsigned g_srcw[E_MAX];       // (src:16 | fp16 weight:16)
__device__ __half   g_h1h [(size_t)NMAX * F_HID];
__device__ __half   g_acc1h[(size_t)NMAX * F_HID];
__device__ __half   g_h2h [(size_t)NMAX * F_OUT];

__device__ __forceinline__ float4 h4_to_f4(uint2 v) {
    __half2 h0 = *reinterpret_cast<__half2*>(&v.x);
    __half2 h1 = *reinterpret_cast<__half2*>(&v.y);
    float2 f0 = __half22float2(h0);
    float2 f1 = __half22float2(h1);
    return make_float4(f0.x, f0.y, f1.x, f1.y);
}
__device__ __forceinline__ uint2 f4_to_h4(float4 v) {
    __half2 a = __floats2half2_rn(v.x, v.y);
    __half2 b = __floats2half2_rn(v.z, v.w);
    uint2 r;
    r.x = *reinterpret_cast<unsigned int*>(&a);
    r.y = *reinterpret_cast<unsigned int*>(&b);
    return r;
}
__device__ __forceinline__ void unpack_sw(unsigned v, int& src, float& w) {
    src = (int)(v >> 16);
    unsigned short hbits = (unsigned short)(v & 0xffffu);
    w = __half2float(__ushort_as_half(hbits));
}

// ---------------- node init (cnt=0, deg=1) + dtype detect in block 0 --------
__global__ void k_node_init(const unsigned int* __restrict__ p, int n) {
    int i = blockIdx.x * blockDim.x + threadIdx.x;
    if (blockIdx.x == 0) {
        // int64 indices (<50000) have all-zero high words; int32 payload doesn't
        unsigned v = p[2 * threadIdx.x + 1];
        int any = __syncthreads_or(v != 0u);
        if (threadIdx.x == 0) g_is64 = any ? 0 : 1;
    }
    if (i < n) { g_cnt[i] = 0; g_deg[i] = 1.0f; }
}

// ---------------- FUSED per-edge: idx convert+pack, histogram, MLP, deg -----
// 2 edges per thread (EPT=2 measured optimum: occ 46%, regs 64).
__global__ __launch_bounds__(256) void k_edge_all(
    const void* __restrict__ ei, const float* __restrict__ ex,
    const float* __restrict__ W1, const float* __restrict__ b1,
    const float* __restrict__ W2, const float* __restrict__ b2, int E, int n)
{
    __shared__ float4 sW1t[EH * 4];
    __shared__ float2 sBW[EH];           // (b1[j], W2[j]) fused -> 1 LDS.64
    __shared__ float sb2;
    int tid = threadIdx.x;
    if (tid < EH * 4) {
        int j = tid >> 2, q = tid & 3;
        sW1t[tid] = make_float4(W1[(4*q+0) * EH + j], W1[(4*q+1) * EH + j],
                                W1[(4*q+2) * EH + j], W1[(4*q+3) * EH + j]);
    }
    if (tid < EH) sBW[tid] = make_float2(b1[tid], W2[tid]);
    if (tid == 0) sb2 = b2[0];
    __syncthreads();

    int t  = blockIdx.x * blockDim.x + tid;
    int e0 = t * 2;
    if (e0 >= E) return;
    int e1 = e0 + 1;
    bool has1 = (e1 < E);

    // ---- load + clamp indices (row, col) for both edges ----
    int r0, c0, r1 = 0, c1 = 0;
    if (g_is64) {
        const long long* p = (const long long*)ei;
        r0 = (int)p[e0]; c0 = (int)p[E + e0];
        if (has1) { r1 = (int)p[e1]; c1 = (int)p[E + e1]; }
    } else {
        const int* p = (const int*)ei;
        r0 = p[e0]; c0 = p[E + e0];
        if (has1) { r1 = p[e1]; c1 = p[E + e1]; }
    }
    r0 = r0 < 0 ? 0 : (r0 >= n ? n - 1 : r0);
    c0 = c0 < 0 ? 0 : (c0 >= n ? n - 1 : c0);
    g_pack[e0] = ((unsigned)r0 << 16) | (unsigned)c0;
    atomicAdd(&g_cnt[c0], 1);
    if (has1) {
        r1 = r1 < 0 ? 0 : (r1 >= n ? n - 1 : r1);
        c1 = c1 < 0 ? 0 : (c1 >= n ? n - 1 : c1);
        g_pack[e1] = ((unsigned)r1 << 16) | (unsigned)c1;
        atomicAdd(&g_cnt[c1], 1);
    }

    // ---- MLP ----
    float4 x0[4], x1[4];
    const float4* ex4 = (const float4*)ex;
#pragma unroll
    for (int i = 0; i < 4; i++) x0[i] = ex4[(size_t)e0 * 4 + i];
    if (has1) {
#pragma unroll
        for (int i = 0; i < 4; i++) x1[i] = ex4[(size_t)e1 * 4 + i];
    } else {
#pragma unroll
        for (int i = 0; i < 4; i++) x1[i] = make_float4(0.f, 0.f, 0.f, 0.f);
    }

    float z0 = sb2, z1 = sb2;
#pragma unroll 2
    for (int j = 0; j < EH; j++) {
        float2 bw = sBW[j];
        float a0 = bw.x, a1 = bw.x;
#pragma unroll
        for (int q = 0; q < 4; q++) {
            float4 w = sW1t[j * 4 + q];
            a0 = fmaf(x0[q].x, w.x, a0); a1 = fmaf(x1[q].x, w.x, a1);
            a0 = fmaf(x0[q].y, w.y, a0); a1 = fmaf(x1[q].y, w.y, a1);
            a0 = fmaf(x0[q].z, w.z, a0); a1 = fmaf(x1[q].z, w.z, a1);
            a0 = fmaf(x0[q].w, w.w, a0); a1 = fmaf(x1[q].w, w.w, a1);
        }
        a0 = fmaxf(a0, 0.0f); a1 = fmaxf(a1, 0.0f);
        z0 = fmaf(a0, bw.y, z0);
        z1 = fmaf(a1, bw.y, z1);
    }
    float w0 = 1.0f / (1.0f + __expf(-z0));
    g_ew[e0] = w0;
    atomicAdd(&g_deg[c0], w0);
    if (has1) {
        float w1v = 1.0f / (1.0f + __expf(-z1));
        g_ew[e1] = w1v;
        atomicAdd(&g_deg[c1], w1v);
    }
}

// ---------------- scan pass 1: per-block exclusive scan + block sums --------
__global__ __launch_bounds__(SCAN_B) void k_scan1(int n) {
    __shared__ int warp_sums[8];
    int tid = threadIdx.x, lane = tid & 31, wid = tid >> 5;
    int i = blockIdx.x * SCAN_B + tid;
    int v = (i < n) ? g_cnt[i] : 0;
    int incl = v;
#pragma unroll
    for (int o = 1; o < 32; o <<= 1) {
        int t = __shfl_up_sync(0xffffffffu, incl, o);
        if (lane >= o) incl += t;
    }
    if (lane == 31) warp_sums[wid] = incl;
    __syncthreads();
    if (wid == 0 && lane < 8) {
        int ws = warp_sums[lane];
#pragma unroll
        for (int o = 1; o < 8; o <<= 1) {
            int t = __shfl_up_sync(0xffu, ws, o);
            if (lane >= o) ws += t;
        }
        warp_sums[lane] = ws;
    }
    __syncthreads();
    int excl = incl - v + (wid > 0 ? warp_sums[wid - 1] : 0);
    if (i < n) g_rowptr[i] = excl;
    if (tid == SCAN_B - 1) g_bsum[blockIdx.x] = excl + v;
}

// ---------------- scan pass 2: exclusive scan of block sums (1 CTA) ---------
__global__ __launch_bounds__(SCAN_B) void k_scan2(int nblk) {
    __shared__ int s[SCAN_B];
    int tid = threadIdx.x;
    s[tid] = (tid < nblk) ? g_bsum[tid] : 0;
    __syncthreads();
    for (int o = 1; o < SCAN_B; o <<= 1) {
        int t = (tid >= o) ? s[tid - o] : 0;
        __syncthreads();
        s[tid] += t;
        __syncthreads();
    }
    if (tid < nblk) g_bsum[tid] = (tid > 0) ? s[tid - 1] : 0;  // exclusive
}

// ---------------- scan pass 3: offsets + cursor + dinv (deg final here) -----
__global__ __launch_bounds__(SCAN_B) void k_scan3(int n, int E) {
    int i = blockIdx.x * SCAN_B + threadIdx.x;
    if (i < n) {
        int v = g_rowptr[i] + g_bsum[blockIdx.x];
        g_rowptr[i] = v;
        g_cursor[i] = v;
        float d = g_deg[i];
        g_dinv[i] = (d > 0.0f) ? rsqrtf(d) : 0.0f;
    }
    if (i == 0) g_rowptr[n] = E;
}

// ---------------- build CSR: scatter packed (src|w) into slot of dst --------
__global__ void k_permute(int E) {
    int e = blockIdx.x * blockDim.x + threadIdx.x;
    if (e >= E) return;
    unsigned pk = g_pack[e];
    int r = (int)(pk >> 16), c = (int)(pk & 0xffffu);
    float w = g_ew[e] * g_dinv[r] * g_dinv[c];
    int pos = atomicAdd(&g_cursor[c], 1);
    unsigned hw = (unsigned)__half_as_ushort(__float2half_rn(w));
    g_srcw[pos] = ((unsigned)r << 16) | hw;
}

// ---------------- h1 = x @ Wg1  (50000x128 @ 128x128) -> fp16 ---------------
#define G1_ROWS 32
__global__ __launch_bounds__(128) void k_gemm1(
    const float* __restrict__ x, const float* __restrict__ W, int n)
{
    __shared__ float4 xs[G1_ROWS * 32];
    int r0  = blockIdx.x * G1_ROWS;
    int tid = threadIdx.x;
    for (int i = tid; i < G1_ROWS * 32; i += 128) {
        int rr = i >> 5, kk = i & 31;
        int row = r0 + rr;
        xs[i] = (row < n) ? ((const float4*)x)[(size_t)row * 32 + kk]
                          : make_float4(0.f, 0.f, 0.f, 0.f);
    }
    __syncthreads();

    int j = tid;
    float acc[G1_ROWS];
#pragma unroll
    for (int r = 0; r < G1_ROWS; r++) acc[r] = 0.0f;

    for (int k4 = 0; k4 < 32; k4++) {
        float w0 = W[(k4*4+0) * F_HID + j];
        float w1 = W[(k4*4+1) * F_HID + j];
        float w2 = W[(k4*4+2) * F_HID + j];
        float w3 = W[(k4*4+3) * F_HID + j];
#pragma unroll
        for (int r = 0; r < G1_ROWS; r++) {
            float4 xv = xs[r * 32 + k4];
            acc[r] = fmaf(xv.x, w0, fmaf(xv.y, w1, fmaf(xv.z, w2, fmaf(xv.w, w3, acc[r]))));
        }
    }
#pragma unroll
    for (int r = 0; r < G1_ROWS; r++) {
        int row = r0 + r;
        if (row < n) g_h1h[(size_t)row * F_HID + j] = __float2half_rn(acc[r]);
    }
}

// ---------------- conv1 gather: acc1 = relu(bg1 + dinv^2*h1 + sum w*h1[src])-
// 4-way unrolled edge loop with 4 accumulator chains.
__global__ __launch_bounds__(256) void k_gather1(const float* __restrict__ bg1, int n)
{
    int c    = (blockIdx.x * blockDim.x + threadIdx.x) >> 5;
    int lane = threadIdx.x & 31;
    if (c >= n) return;
    float di = g_dinv[c];
    float sl = di * di;

    float4 acc = ((const float4*)bg1)[lane];
    {
        const uint2* rp = (const uint2*)(g_h1h + (size_t)c * F_HID);
        float4 hv = h4_to_f4(rp[lane]);
        acc.x = fmaf(sl, hv.x, acc.x);
        acc.y = fmaf(sl, hv.y, acc.y);
        acc.z = fmaf(sl, hv.z, acc.z);
        acc.w = fmaf(sl, hv.w, acc.w);
    }

    int beg = g_rowptr[c], end = g_rowptr[c + 1];
    float4 a1 = make_float4(0.f, 0.f, 0.f, 0.f);
    float4 a2 = make_float4(0.f, 0.f, 0.f, 0.f);
    float4 a3 = make_float4(0.f, 0.f, 0.f, 0.f);
    int cnt = end - beg;
    int end4 = beg + (cnt & ~3);
    int j = beg;
    for (; j < end4; j += 4) {
        int s0, s1, s2, s3; float w0, w1, w2, w3;
        unpack_sw(g_srcw[j],     s0, w0);
        unpack_sw(g_srcw[j + 1], s1, w1);
        unpack_sw(g_srcw[j + 2], s2, w2);
        unpack_sw(g_srcw[j + 3], s3, w3);
        float4 v0 = h4_to_f4(((const uint2*)(g_h1h + (size_t)s0 * F_HID))[lane]);
        float4 v1 = h4_to_f4(((const uint2*)(g_h1h + (size_t)s1 * F_HID))[lane]);
        float4 v2 = h4_to_f4(((const uint2*)(g_h1h + (size_t)s2 * F_HID))[lane]);
        float4 v3 = h4_to_f4(((const uint2*)(g_h1h + (size_t)s3 * F_HID))[lane]);
        acc.x = fmaf(w0, v0.x, acc.x);  a1.x = fmaf(w1, v1.x, a1.x);
        acc.y = fmaf(w0, v0.y, acc.y);  a1.y = fmaf(w1, v1.y, a1.y);
        acc.z = fmaf(w0, v0.z, acc.z);  a1.z = fmaf(w1, v1.z, a1.z);
        acc.w = fmaf(w0, v0.w, acc.w);  a1.w = fmaf(w1, v1.w, a1.w);
        a2.x = fmaf(w2, v2.x, a2.x);    a3.x = fmaf(w3, v3.x, a3.x);
        a2.y = fmaf(w2, v2.y, a2.y);    a3.y = fmaf(w3, v3.y, a3.y);
        a2.z = fmaf(w2, v2.z, a2.z);    a3.z = fmaf(w3, v3.z, a3.z);
        a2.w = fmaf(w2, v2.w, a2.w);    a3.w = fmaf(w3, v3.w, a3.w);
    }
    for (; j < end; j++) {
        int s0; float w0;
        unpack_sw(g_srcw[j], s0, w0);
        float4 v0 = h4_to_f4(((const uint2*)(g_h1h + (size_t)s0 * F_HID))[lane]);
        acc.x = fmaf(w0, v0.x, acc.x);
        acc.y = fmaf(w0, v0.y, acc.y);
        acc.z = fmaf(w0, v0.z, acc.z);
        acc.w = fmaf(w0, v0.w, acc.w);
    }
    acc.x = fmaxf(acc.x + a1.x + a2.x + a3.x, 0.f);
    acc.y = fmaxf(acc.y + a1.y + a2.y + a3.y, 0.f);
    acc.z = fmaxf(acc.z + a1.z + a2.z + a3.z, 0.f);
    acc.w = fmaxf(acc.w + a1.w + a2.w + a3.w, 0.f);
    ((uint2*)(g_acc1h + (size_t)c * F_HID))[lane] = f4_to_h4(acc);
}

// ---------------- h2 = acc1 @ Wg2 (acc1 fp16, already ReLU'd) -> fp16 -------
__global__ __launch_bounds__(128) void k_gemm2(const float* __restrict__ W, int n)
{
    __shared__ float sw[F_HID * F_OUT];
    int tid = threadIdx.x;
    for (int i = tid; i < F_HID * F_OUT; i += 128) sw[i] = W[i];
    __syncthreads();

    int warp = tid >> 5, lane = tid & 31;
    int rbase = blockIdx.x * 16 + warp * 4;
    float accA[4] = {0.f, 0.f, 0.f, 0.f};
    float accB[4] = {0.f, 0.f, 0.f, 0.f};
    bool hiLane = (lane < 8);

    for (int k4 = 0; k4 < 32; k4++) {
        float w0[4], w1[4];
#pragma unroll
        for (int i = 0; i < 4; i++) {
            int k = k4 * 4 + i;
            w0[i] = sw[k * F_OUT + lane];
            w1[i] = hiLane ? sw[k * F_OUT + 32 + lane] : 0.0f;
        }
#pragma unroll
        for (int r = 0; r < 4; r++) {
            int rowi = rbase + r;
            if (rowi < n) {
                const uint2* xp = (const uint2*)(g_acc1h + (size_t)rowi * F_HID);
                float4 xv = h4_to_f4(xp[k4]);
                accA[r] = fmaf(xv.x, w0[0], fmaf(xv.y, w0[1], fmaf(xv.z, w0[2], fmaf(xv.w, w0[3], accA[r]))));
                accB[r] = fmaf(xv.x, w1[0], fmaf(xv.y, w1[1], fmaf(xv.z, w1[2], fmaf(xv.w, w1[3], accB[r]))));
            }
        }
    }
#pragma unroll
    for (int r = 0; r < 4; r++) {
        int rowi = rbase + r;
        if (rowi < n) {
            g_h2h[(size_t)rowi * F_OUT + lane] = __float2half_rn(accA[r]);
            if (hiLane) g_h2h[(size_t)rowi * F_OUT + 32 + lane] = __float2half_rn(accB[r]);
        }
    }
}

// ---------------- conv2 gather: out = bg2 + dinv^2*h2 + sum w*h2[src] -------
__global__ __launch_bounds__(256) void k_gather2(float* __restrict__ out,
                                                 const float* __restrict__ bg2, int n)
{
    int c    = (blockIdx.x * blockDim.x + threadIdx.x) >> 5;
    int lane = threadIdx.x & 31;
    if (c >= n || lane >= 20) return;
    float di = g_dinv[c];
    float sl = di * di;

    float2 acc = ((const float2*)bg2)[lane];
    {
        const __half2* rp = (const __half2*)(g_h2h + (size_t)c * F_OUT);
        float2 hv = __half22float2(rp[lane]);
        acc.x = fmaf(sl, hv.x, acc.x);
        acc.y = fmaf(sl, hv.y, acc.y);
    }
    float2 a2 = make_float2(0.f, 0.f);

    int beg = g_rowptr[c], end = g_rowptr[c + 1];
    int j = beg;
    for (; j + 1 < end; j += 2) {
        int s0, s1; float w0, w1;
        unpack_sw(g_srcw[j], s0, w0);
        unpack_sw(g_srcw[j + 1], s1, w1);
        const __half2* p0 = (const __half2*)(g_h2h + (size_t)s0 * F_OUT);
        const __half2* p1 = (const __half2*)(g_h2h + (size_t)s1 * F_OUT);
        float2 v0 = __half22float2(p0[lane]);
        float2 v1 = __half22float2(p1[lane]);
        acc.x = fmaf(w0, v0.x, acc.x);  a2.x = fmaf(w1, v1.x, a2.x);
        acc.y = fmaf(w0, v0.y, acc.y);  a2.y = fmaf(w1, v1.y, a2.y);
    }
    if (j < end) {
        int s0; float w0;
        unpack_sw(g_srcw[j], s0, w0);
        const __half2* p0 = (const __half2*)(g_h2h + (size_t)s0 * F_OUT);
        float2 v0 = __half22float2(p0[lane]);
        acc.x = fmaf(w0, v0.x, acc.x);
        acc.y = fmaf(w0, v0.y, acc.y);
    }
    acc.x += a2.x;
    acc.y += a2.y;
    ((float2*)(out + (size_t)c * F_OUT))[lane] = acc;
}

// ---------------- launch -----------------------------------------------------
extern "C" void kernel_launch(void* const* d_in, const int* in_sizes, int n_in,
                              void* d_out, int out_size)
{
    const float* x   = (const float*)d_in[0];
    const void*  ei  = d_in[1];
    const float* ex  = (const float*)d_in[2];
    const float* W1  = (const float*)d_in[3];
    const float* b1  = (const float*)d_in[4];
    const float* W2  = (const float*)d_in[5];
    const float* b2  = (const float*)d_in[6];
    const float* Wg1 = (const float*)d_in[7];
    const float* bg1 = (const float*)d_in[8];
    const float* Wg2 = (const float*)d_in[9];
    const float* bg2 = (const float*)d_in[10];
    float* out = (float*)d_out;

    int n = in_sizes[0] / F_IN;       // 50000
    int E = in_sizes[2] / EF;         // 1600000
    int nblk = (n + SCAN_B - 1) / SCAN_B;

    // lazy-once side stream + events (same work every call; capture-safe fork/join)
    static cudaStream_t s2 = nullptr;
    static cudaEvent_t  evFork = nullptr, evJoin = nullptr;
    if (s2 == nullptr) {
        cudaStreamCreateWithFlags(&s2, cudaStreamNonBlocking);
        cudaEventCreateWithFlags(&evFork, cudaEventDisableTiming);
        cudaEventCreateWithFlags(&evJoin, cudaEventDisableTiming);
    }

    // fork: gemm1 depends only on x,Wg1 — run on side stream
    cudaEventRecord(evFork, 0);
    cudaStreamWaitEvent(s2, evFork, 0);
    k_gemm1<<<(n + G1_ROWS - 1) / G1_ROWS, 128, 0, s2>>>(x, Wg1, n);
    cudaEventRecord(evJoin, s2);

    // main stream: fused edge pipeline (detect folded into node_init block 0)
    k_node_init<<<(n + 255) / 256, 256>>>((const unsigned int*)ei, n);

    int mlp_threads = (E + 1) / 2;
    k_edge_all<<<(mlp_threads + 255) / 256, 256>>>(ei, ex, W1, b1, W2, b2, E, n);

    k_scan1<<<nblk, SCAN_B>>>(n);
    k_scan2<<<1, SCAN_B>>>(nblk);
    k_scan3<<<nblk, SCAN_B>>>(n, E);

    k_permute<<<(E + 255) / 256, 256>>>(E);

    // join: gather1 needs both gemm1 (h1) and permute (CSR)
    cudaStreamWaitEvent(0, evJoin, 0);
    k_gather1<<<(n * 32 + 255) / 256, 256>>>(bg1, n);

    k_gemm2<<<(n + 15) / 16, 128>>>(Wg2, n);

    k_gather2<<<(n * 32 + 255) / 256, 256>>>(out, bg2, n);
}

// round 13
// speedup vs baseline: 1.0819x; 1.0819x over previous
#include <cuda_runtime.h>
#include <cuda_fp16.h>
#include <mma.h>
#include <math.h>

using namespace nvcuda;

#define NMAX   50000
#define E_MAX  1600000
#define F_IN   128
#define F_HID  128
#define F_OUT  40
#define EF     16
#define EH     32
#define SCAN_B 256
#define TILE_E 512     // edges per CTA in edge kernel
#define EX_LD  24      // padded halfs per staged ex row (48B, ldmatrix-legal)
#define C_LD   36      // padded floats per staged c row (16B-multiple, conflict-light)

// ---------------- scratch (static device globals; no allocs allowed) --------
__device__ int      g_is64;
__device__ int      g_idx [2 * E_MAX];   // row[E], col[E] as int32 (clamped)
__device__ float    g_ew  [E_MAX];
__device__ float    g_deg [NMAX];
__device__ float    g_dinv[NMAX];
__device__ int      g_cnt [NMAX];
__device__ int      g_rowptr[NMAX + 1];
__device__ int      g_cursor[NMAX];
__device__ int      g_bsum[((NMAX + SCAN_B - 1) / SCAN_B) + 1];
__device__ unsigned g_srcw[E_MAX];       // (src:16 | fp16 weight:16)
__device__ __half   g_h1h [(size_t)NMAX * F_HID];
__device__ __half   g_acc1h[(size_t)NMAX * F_HID];
__device__ __half   g_h2h [(size_t)NMAX * F_OUT];

__device__ __forceinline__ float4 h4_to_f4(uint2 v) {
    __half2 h0 = *reinterpret_cast<__half2*>(&v.x);
    __half2 h1 = *reinterpret_cast<__half2*>(&v.y);
    float2 f0 = __half22float2(h0);
    float2 f1 = __half22float2(h1);
    return make_float4(f0.x, f0.y, f1.x, f1.y);
}
__device__ __forceinline__ uint2 f4_to_h4(float4 v) {
    __half2 a = __floats2half2_rn(v.x, v.y);
    __half2 b = __floats2half2_rn(v.z, v.w);
    uint2 r;
    r.x = *reinterpret_cast<unsigned int*>(&a);
    r.y = *reinterpret_cast<unsigned int*>(&b);
    return r;
}
__device__ __forceinline__ void unpack_sw(unsigned v, int& src, float& w) {
    src = (int)(v >> 16);
    unsigned short hbits = (unsigned short)(v & 0xffffu);
    w = __half2float(__ushort_as_half(hbits));
}

// ---------------- node init (cnt=0, deg=1) + dtype detect in block 0 --------
__global__ void k_node_init(const unsigned int* __restrict__ p, int n) {
    int i = blockIdx.x * blockDim.x + threadIdx.x;
    if (blockIdx.x == 0) {
        // int64 indices (<50000) have all-zero high words; int32 payload doesn't
        unsigned v = p[2 * threadIdx.x + 1];
        int any = __syncthreads_or(v != 0u);
        if (threadIdx.x == 0) g_is64 = any ? 0 : 1;
    }
    if (i < n) { g_cnt[i] = 0; g_deg[i] = 1.0f; }
}

// ---------------- FUSED per-edge: idx convert, histogram, tensor-core MLP ---
// CTA handles TILE_E=512 edges. Layer1 via wmma m16n16k16 (fp16 in, fp32 acc).
__global__ __launch_bounds__(256) void k_edge_all(
    const void* __restrict__ ei, const float* __restrict__ ex,
    const float* __restrict__ W1, const float* __restrict__ b1,
    const float* __restrict__ W2, const float* __restrict__ b2, int E, int n)
{
    __shared__ __half s_exh[TILE_E * EX_LD];      // 24 KB
    __shared__ __half s_w1h[16 * 32];             // 1 KB, row-major ldm 32
    __shared__ float  s_c[8][16 * C_LD];          // 18 KB (per-warp staging)
    __shared__ float  s_b1[EH];
    __shared__ float  s_w2[EH];
    __shared__ float  s_b2;

    int tid = threadIdx.x;
    int e_base = blockIdx.x * TILE_E;

    // ---- stage weights ----
    {
        int i0 = tid * 2;   // 512 halfs, 256 threads
        s_w1h[i0]     = __float2half_rn(W1[i0]);
        s_w1h[i0 + 1] = __float2half_rn(W1[i0 + 1]);
    }
    if (tid < EH) { s_b1[tid] = b1[tid]; s_w2[tid] = W2[tid]; }
    if (tid == 0) s_b2 = b2[0];

    // ---- idx convert+clamp+store+histogram (2 edges/thread) ----
    {
        int e0 = e_base + tid * 2;
        int e1 = e0 + 1;
        if (e0 < E) {
            int r0, c0;
            if (g_is64) { const long long* p = (const long long*)ei;
                          r0 = (int)p[e0]; c0 = (int)p[E + e0]; }
            else        { const int* p = (const int*)ei;
                          r0 = p[e0]; c0 = p[E + e0]; }
            r0 = r0 < 0 ? 0 : (r0 >= n ? n - 1 : r0);
            c0 = c0 < 0 ? 0 : (c0 >= n ? n - 1 : c0);
            g_idx[e0] = r0; g_idx[E + e0] = c0;
            atomicAdd(&g_cnt[c0], 1);
            if (e1 < E) {
                int r1, c1;
                if (g_is64) { const long long* p = (const long long*)ei;
                              r1 = (int)p[e1]; c1 = (int)p[E + e1]; }
                else        { const int* p = (const int*)ei;
                              r1 = p[e1]; c1 = p[E + e1]; }
                r1 = r1 < 0 ? 0 : (r1 >= n ? n - 1 : r1);
                c1 = c1 < 0 ? 0 : (c1 >= n ? n - 1 : c1);
                g_idx[e1] = r1; g_idx[E + e1] = c1;
                atomicAdd(&g_cnt[c1], 1);
            }
        }
    }

    // ---- stage ex tile as fp16 (coalesced float4 loads) ----
    {
        const float4* ex4 = (const float4*)ex;
#pragma unroll
        for (int it = 0; it < 8; it++) {
            int f = tid + it * 256;          // [0, 2048)
            int e_loc = f >> 2, q = f & 3;
            int e = e_base + e_loc;
            float4 v = (e < E) ? ex4[(size_t)e * 4 + q]
                               : make_float4(0.f, 0.f, 0.f, 0.f);
            __half2* dst = (__half2*)(s_exh + e_loc * EX_LD + q * 4);
            dst[0] = __floats2half2_rn(v.x, v.y);
            dst[1] = __floats2half2_rn(v.z, v.w);
        }
    }
    __syncthreads();

    // ---- per-warp: 4 tiles of 16 edges via wmma ----
    int wid = tid >> 5, lane = tid & 31;
    wmma::fragment<wmma::matrix_b, 16, 16, 16, __half, wmma::row_major> bf0, bf1;
    wmma::load_matrix_sync(bf0, s_w1h,      32);
    wmma::load_matrix_sync(bf1, s_w1h + 16, 32);

    float* cbuf = s_c[wid];
    int row = lane & 15, hh = lane >> 4;
    const float* bb = s_b1 + hh * 16;
    const float* ww = s_w2 + hh * 16;

#pragma unroll
    for (int t4 = 0; t4 < 4; t4++) {
        int tile = wid * 4 + t4;
        wmma::fragment<wmma::matrix_a, 16, 16, 16, __half, wmma::row_major> af;
        wmma::load_matrix_sync(af, s_exh + tile * 16 * EX_LD, EX_LD);
        wmma::fragment<wmma::accumulator, 16, 16, 16, float> c0, c1;
        wmma::fill_fragment(c0, 0.f);
        wmma::fill_fragment(c1, 0.f);
        wmma::mma_sync(c0, af, bf0, c0);
        wmma::mma_sync(c1, af, bf1, c1);
        wmma::store_matrix_sync(cbuf,      c0, C_LD, wmma::mem_row_major);
        wmma::store_matrix_sync(cbuf + 16, c1, C_LD, wmma::mem_row_major);
        __syncwarp();

        // layer2: lane = (hh, row) handles 16 of the 32 hidden units of its row
        int e = e_base + tile * 16 + row;
        const float* crow = cbuf + row * C_LD + hh * 16;
        float z = 0.f;
#pragma unroll
        for (int k = 0; k < 16; k++) {
            float a = crow[k] + bb[k];
            z = fmaf(fmaxf(a, 0.f), ww[k], z);
        }
        z += __shfl_xor_sync(0xffffffffu, z, 16);
        if (hh == 0 && e < E) {
            float w = 1.0f / (1.0f + __expf(-(z + s_b2)));
            g_ew[e] = w;
            atomicAdd(&g_deg[g_idx[E + e]], w);
        }
        __syncwarp();   // done reading cbuf before next tile overwrites it
    }
}

// ---------------- scan pass 1: per-block exclusive scan + block sums --------
__global__ __launch_bounds__(SCAN_B) void k_scan1(int n) {
    __shared__ int warp_sums[8];
    int tid = threadIdx.x, lane = tid & 31, wid = tid >> 5;
    int i = blockIdx.x * SCAN_B + tid;
    int v = (i < n) ? g_cnt[i] : 0;
    int incl = v;
#pragma unroll
    for (int o = 1; o < 32; o <<= 1) {
        int t = __shfl_up_sync(0xffffffffu, incl, o);
        if (lane >= o) incl += t;
    }
    if (lane == 31) warp_sums[wid] = incl;
    __syncthreads();
    if (wid == 0 && lane < 8) {
        int ws = warp_sums[lane];
#pragma unroll
        for (int o = 1; o < 8; o <<= 1) {
            int t = __shfl_up_sync(0xffu, ws, o);
            if (lane >= o) ws += t;
        }
        warp_sums[lane] = ws;
    }
    __syncthreads();
    int excl = incl - v + (wid > 0 ? warp_sums[wid - 1] : 0);
    if (i < n) g_rowptr[i] = excl;
    if (tid == SCAN_B - 1) g_bsum[blockIdx.x] = excl + v;
}

// ---------------- scan pass 2: exclusive scan of block sums (1 CTA) ---------
__global__ __launch_bounds__(SCAN_B) void k_scan2(int nblk) {
    __shared__ int s[SCAN_B];
    int tid = threadIdx.x;
    s[tid] = (tid < nblk) ? g_bsum[tid] : 0;
    __syncthreads();
    for (int o = 1; o < SCAN_B; o <<= 1) {
        int t = (tid >= o) ? s[tid - o] : 0;
        __syncthreads();
        s[tid] += t;
        __syncthreads();
    }
    if (tid < nblk) g_bsum[tid] = (tid > 0) ? s[tid - 1] : 0;  // exclusive
}

// ---------------- scan pass 3: offsets + cursor + dinv (deg final here) -----
__global__ __launch_bounds__(SCAN_B) void k_scan3(int n, int E) {
    int i = blockIdx.x * SCAN_B + threadIdx.x;
    if (i < n) {
        int v = g_rowptr[i] + g_bsum[blockIdx.x];
        g_rowptr[i] = v;
        g_cursor[i] = v;
        float d = g_deg[i];
        g_dinv[i] = (d > 0.0f) ? rsqrtf(d) : 0.0f;
    }
    if (i == 0) g_rowptr[n] = E;
}

// ---------------- build CSR: scatter packed (src|w) into slot of dst --------
__global__ void k_permute(int E) {
    int e = blockIdx.x * blockDim.x + threadIdx.x;
    if (e >= E) return;
    int r = g_idx[e], c = g_idx[E + e];
    float w = g_ew[e] * g_dinv[r] * g_dinv[c];
    int pos = atomicAdd(&g_cursor[c], 1);
    unsigned hw = (unsigned)__half_as_ushort(__float2half_rn(w));
    g_srcw[pos] = ((unsigned)r << 16) | hw;
}

// ---------------- h1 = x @ Wg1  (50000x128 @ 128x128) -> fp16 ---------------
#define G1_ROWS 32
__global__ __launch_bounds__(128) void k_gemm1(
    const float* __restrict__ x, const float* __restrict__ W, int n)
{
    __shared__ float4 xs[G1_ROWS * 32];
    int r0  = blockIdx.x * G1_ROWS;
    int tid = threadIdx.x;
    for (int i = tid; i < G1_ROWS * 32; i += 128) {
        int rr = i >> 5, kk = i & 31;
        int row = r0 + rr;
        xs[i] = (row < n) ? ((const float4*)x)[(size_t)row * 32 + kk]
                          : make_float4(0.f, 0.f, 0.f, 0.f);
    }
    __syncthreads();

    int j = tid;
    float acc[G1_ROWS];
#pragma unroll
    for (int r = 0; r < G1_ROWS; r++) acc[r] = 0.0f;

    for (int k4 = 0; k4 < 32; k4++) {
        float w0 = W[(k4*4+0) * F_HID + j];
        float w1 = W[(k4*4+1) * F_HID + j];
        float w2 = W[(k4*4+2) * F_HID + j];
        float w3 = W[(k4*4+3) * F_HID + j];
#pragma unroll
        for (int r = 0; r < G1_ROWS; r++) {
            float4 xv = xs[r * 32 + k4];
            acc[r] = fmaf(xv.x, w0, fmaf(xv.y, w1, fmaf(xv.z, w2, fmaf(xv.w, w3, acc[r]))));
        }
    }
#pragma unroll
    for (int r = 0; r < G1_ROWS; r++) {
        int row = r0 + r;
        if (row < n) g_h1h[(size_t)row * F_HID + j] = __float2half_rn(acc[r]);
    }
}

// ---------------- conv1 gather: acc1 = relu(bg1 + dinv^2*h1 + sum w*h1[src])-
__global__ __launch_bounds__(256) void k_gather1(const float* __restrict__ bg1, int n)
{
    int c    = (blockIdx.x * blockDim.x + threadIdx.x) >> 5;
    int lane = threadIdx.x & 31;
    if (c >= n) return;
    float di = g_dinv[c];
    float sl = di * di;

    float4 acc = ((const float4*)bg1)[lane];
    {
        const uint2* rp = (const uint2*)(g_h1h + (size_t)c * F_HID);
        float4 hv = h4_to_f4(rp[lane]);
        acc.x = fmaf(sl, hv.x, acc.x);
        acc.y = fmaf(sl, hv.y, acc.y);
        acc.z = fmaf(sl, hv.z, acc.z);
        acc.w = fmaf(sl, hv.w, acc.w);
    }

    int beg = g_rowptr[c], end = g_rowptr[c + 1];
    float4 a2 = make_float4(0.f, 0.f, 0.f, 0.f);
    int j = beg;
    for (; j + 1 < end; j += 2) {
        unsigned m0 = g_srcw[j];
        unsigned m1 = g_srcw[j + 1];
        int s0, s1; float w0, w1;
        unpack_sw(m0, s0, w0);
        unpack_sw(m1, s1, w1);
        const uint2* p0 = (const uint2*)(g_h1h + (size_t)s0 * F_HID);
        const uint2* p1 = (const uint2*)(g_h1h + (size_t)s1 * F_HID);
        float4 v0 = h4_to_f4(p0[lane]);
        float4 v1 = h4_to_f4(p1[lane]);
        acc.x = fmaf(w0, v0.x, acc.x);  a2.x = fmaf(w1, v1.x, a2.x);
        acc.y = fmaf(w0, v0.y, acc.y);  a2.y = fmaf(w1, v1.y, a2.y);
        acc.z = fmaf(w0, v0.z, acc.z);  a2.z = fmaf(w1, v1.z, a2.z);
        acc.w = fmaf(w0, v0.w, acc.w);  a2.w = fmaf(w1, v1.w, a2.w);
    }
    if (j < end) {
        int s0; float w0;
        unpack_sw(g_srcw[j], s0, w0);
        const uint2* p0 = (const uint2*)(g_h1h + (size_t)s0 * F_HID);
        float4 v0 = h4_to_f4(p0[lane]);
        acc.x = fmaf(w0, v0.x, acc.x);
        acc.y = fmaf(w0, v0.y, acc.y);
        acc.z = fmaf(w0, v0.z, acc.z);
        acc.w = fmaf(w0, v0.w, acc.w);
    }
    acc.x = fmaxf(acc.x + a2.x, 0.f);
    acc.y = fmaxf(acc.y + a2.y, 0.f);
    acc.z = fmaxf(acc.z + a2.z, 0.f);
    acc.w = fmaxf(acc.w + a2.w, 0.f);
    ((uint2*)(g_acc1h + (size_t)c * F_HID))[lane] = f4_to_h4(acc);
}

// ---------------- h2 = acc1 @ Wg2 (acc1 fp16, already ReLU'd) -> fp16 -------
__global__ __launch_bounds__(128) void k_gemm2(const float* __restrict__ W, int n)
{
    __shared__ float sw[F_HID * F_OUT];
    int tid = threadIdx.x;
    for (int i = tid; i < F_HID * F_OUT; i += 128) sw[i] = W[i];
    __syncthreads();

    int warp = tid >> 5, lane = tid & 31;
    int rbase = blockIdx.x * 16 + warp * 4;
    float accA[4] = {0.f, 0.f, 0.f, 0.f};
    float accB[4] = {0.f, 0.f, 0.f, 0.f};
    bool hiLane = (lane < 8);

    for (int k4 = 0; k4 < 32; k4++) {
        float w0[4], w1[4];
#pragma unroll
        for (int i = 0; i < 4; i++) {
            int k = k4 * 4 + i;
            w0[i] = sw[k * F_OUT + lane];
            w1[i] = hiLane ? sw[k * F_OUT + 32 + lane] : 0.0f;
        }
#pragma unroll
        for (int r = 0; r < 4; r++) {
            int rowi = rbase + r;
            if (rowi < n) {
                const uint2* xp = (const uint2*)(g_acc1h + (size_t)rowi * F_HID);
                float4 xv = h4_to_f4(xp[k4]);
                accA[r] = fmaf(xv.x, w0[0], fmaf(xv.y, w0[1], fmaf(xv.z, w0[2], fmaf(xv.w, w0[3], accA[r]))));
                accB[r] = fmaf(xv.x, w1[0], fmaf(xv.y, w1[1], fmaf(xv.z, w1[2], fmaf(xv.w, w1[3], accB[r]))));
            }
        }
    }
#pragma unroll
    for (int r = 0; r < 4; r++) {
        int rowi = rbase + r;
        if (rowi < n) {
            g_h2h[(size_t)rowi * F_OUT + lane] = __float2half_rn(accA[r]);
            if (hiLane) g_h2h[(size_t)rowi * F_OUT + 32 + lane] = __float2half_rn(accB[r]);
        }
    }
}

// ---------------- conv2 gather: out = bg2 + dinv^2*h2 + sum w*h2[src] -------
__global__ __launch_bounds__(256) void k_gather2(float* __restrict__ out,
                                                 const float* __restrict__ bg2, int n)
{
    int c    = (blockIdx.x * blockDim.x + threadIdx.x) >> 5;
    int lane = threadIdx.x & 31;
    if (c >= n || lane >= 20) return;
    float di = g_dinv[c];
    float sl = di * di;

    float2 acc = ((const float2*)bg2)[lane];
    {
        const __half2* rp = (const __half2*)(g_h2h + (size_t)c * F_OUT);
        float2 hv = __half22float2(rp[lane]);
        acc.x = fmaf(sl, hv.x, acc.x);
        acc.y = fmaf(sl, hv.y, acc.y);
    }
    float2 a2 = make_float2(0.f, 0.f);

    int beg = g_rowptr[c], end = g_rowptr[c + 1];
    int j = beg;
    for (; j + 1 < end; j += 2) {
        int s0, s1; float w0, w1;
        unpack_sw(g_srcw[j], s0, w0);
        unpack_sw(g_srcw[j + 1], s1, w1);
        const __half2* p0 = (const __half2*)(g_h2h + (size_t)s0 * F_OUT);
        const __half2* p1 = (const __half2*)(g_h2h + (size_t)s1 * F_OUT);
        float2 v0 = __half22float2(p0[lane]);
        float2 v1 = __half22float2(p1[lane]);
        acc.x = fmaf(w0, v0.x, acc.x);  a2.x = fmaf(w1, v1.x, a2.x);
        acc.y = fmaf(w0, v0.y, acc.y);  a2.y = fmaf(w1, v1.y, a2.y);
    }
    if (j < end) {
        int s0; float w0;
        unpack_sw(g_srcw[j], s0, w0);
        const __half2* p0 = (const __half2*)(g_h2h + (size_t)s0 * F_OUT);
        float2 v0 = __half22float2(p0[lane]);
        acc.x = fmaf(w0, v0.x, acc.x);
        acc.y = fmaf(w0, v0.y, acc.y);
    }
    acc.x += a2.x;
    acc.y += a2.y;
    ((float2*)(out + (size_t)c * F_OUT))[lane] = acc;
}

// ---------------- launch -----------------------------------------------------
extern "C" void kernel_launch(void* const* d_in, const int* in_sizes, int n_in,
                              void* d_out, int out_size)
{
    const float* x   = (const float*)d_in[0];
    const void*  ei  = d_in[1];
    const float* ex  = (const float*)d_in[2];
    const float* W1  = (const float*)d_in[3];
    const float* b1  = (const float*)d_in[4];
    const float* W2  = (const float*)d_in[5];
    const float* b2  = (const float*)d_in[6];
    const float* Wg1 = (const float*)d_in[7];
    const float* bg1 = (const float*)d_in[8];
    const float* Wg2 = (const float*)d_in[9];
    const float* bg2 = (const float*)d_in[10];
    float* out = (float*)d_out;

    int n = in_sizes[0] / F_IN;       // 50000
    int E = in_sizes[2] / EF;         // 1600000
    int nblk = (n + SCAN_B - 1) / SCAN_B;

    // lazy-once side stream + events (same work every call; capture-safe fork/join)
    static cudaStream_t s2 = nullptr;
    static cudaEvent_t  evFork = nullptr, evJoin = nullptr;
    if (s2 == nullptr) {
        cudaStreamCreateWithFlags(&s2, cudaStreamNonBlocking);
        cudaEventCreateWithFlags(&evFork, cudaEventDisableTiming);
        cudaEventCreateWithFlags(&evJoin, cudaEventDisableTiming);
    }

    // fork: gemm1 depends only on x,Wg1 — run on side stream
    cudaEventRecord(evFork, 0);
    cudaStreamWaitEvent(s2, evFork, 0);
    k_gemm1<<<(n + G1_ROWS - 1) / G1_ROWS, 128, 0, s2>>>(x, Wg1, n);
    cudaEventRecord(evJoin, s2);

    // main stream: fused edge pipeline (detect folded into node_init block 0)
    k_node_init<<<(n + 255) / 256, 256>>>((const unsigned int*)ei, n);

    int eblk = (E + TILE_E - 1) / TILE_E;
    k_edge_all<<<eblk, 256>>>(ei, ex, W1, b1, W2, b2, E, n);

    k_scan1<<<nblk, SCAN_B>>>(n);
    k_scan2<<<1, SCAN_B>>>(nblk);
    k_scan3<<<nblk, SCAN_B>>>(n, E);

    k_permute<<<(E + 255) / 256, 256>>>(E);

    // join: gather1 needs both gemm1 (h1) and permute (CSR)
    cudaStreamWaitEvent(0, evJoin, 0);
    k_gather1<<<(n * 32 + 255) / 256, 256>>>(bg1, n);

    k_gemm2<<<(n + 15) / 16, 128>>>(Wg2, n);

    k_gather2<<<(n * 32 + 255) / 256, 256>>>(out, bg2, n);
}